// round 14
// baseline (speedup 1.0000x reference)
#include <cuda_runtime.h>
#include <cuda_fp16.h>
#include <cstdint>

#define BB 2
#define TT 2048
#define CC 1024
#define HH 16
#define DD 64
#define MM (BB*TT)

// ---- projection GEMM tiling ----
#define BM 128
#define BN 128
#define BK 64
#define PADK 72                 // smem row stride in halves (144 B), conflict-free
#define ROWB (PADK*2)           // 144 bytes
#define AH_OFF 0
#define BH_OFF (128*ROWB)       // 18432
#define STAGEB (2*128*ROWB)     // 36864
#define GSMEM_TOTAL (3*STAGEB)  // 110592 B  (x2 CTAs <= carveout)

// ---- attention tiling: AQ=64, 4 warps, 5 CTAs/SM; Q direct-LDG ----
#define AQ  64
#define AKV 64
#define AST 144
#define SK0 0
#define SV0 (2*64*AST)          // 18432 (after 2 K stages)
#define ASMEM (4*64*AST)        // 36864  (x5 CTAs = 184320)

#define SCQ (0.125f * 1.44269504088896340736f)   // 1/sqrt(D) * log2(e)

// ---------------------------------------------------------------------------
// Scratch (allocation-free device globals) — all fp16
// ---------------------------------------------------------------------------
__device__ __align__(256) __half g_qh[MM*CC];    // Q * 0.125*log2e
__device__ __align__(256) __half g_kh[MM*CC];
__device__ __align__(256) __half g_vh[MM*CC];
__device__ __align__(256) __half g_ah[MM*CC];    // A operand (x, later att out)
__device__ __align__(256) __half g_wh[4][CC*CC]; // W transposed [n][k], fp16

// ---------------------------------------------------------------------------
// PTX helpers (baseline sm_80+ features only)
// ---------------------------------------------------------------------------
__device__ __forceinline__ uint32_t smem_u32(const void* p) {
    uint32_t a;
    asm("{ .reg .u64 t; cvta.to.shared.u64 t, %1; cvt.u32.u64 %0, t; }" : "=r"(a) : "l"(p));
    return a;
}
__device__ __forceinline__ void cpa16(uint32_t dst, const void* src) {
    asm volatile("cp.async.cg.shared.global [%0], [%1], 16;" :: "r"(dst), "l"(src));
}
__device__ __forceinline__ void cpa_commit() {
    asm volatile("cp.async.commit_group;" ::: "memory");
}
template<int N>
__device__ __forceinline__ void cpa_wait() {
    asm volatile("cp.async.wait_group %0;" :: "n"(N) : "memory");
}
__device__ __forceinline__ void ldsm4(uint32_t* r, uint32_t addr) {
    asm volatile("ldmatrix.sync.aligned.m8n8.x4.shared.b16 {%0,%1,%2,%3}, [%4];"
        : "=r"(r[0]), "=r"(r[1]), "=r"(r[2]), "=r"(r[3]) : "r"(addr));
}
__device__ __forceinline__ void ldsm4t(uint32_t* r, uint32_t addr) {
    asm volatile("ldmatrix.sync.aligned.m8n8.x4.trans.shared.b16 {%0,%1,%2,%3}, [%4];"
        : "=r"(r[0]), "=r"(r[1]), "=r"(r[2]), "=r"(r[3]) : "r"(addr));
}
__device__ __forceinline__ void mma16816h(float* c, const uint32_t* a,
                                          uint32_t b0, uint32_t b1) {
    asm volatile("mma.sync.aligned.m16n8k16.row.col.f32.f16.f16.f32 "
        "{%0,%1,%2,%3}, {%4,%5,%6,%7}, {%8,%9}, {%0,%1,%2,%3};"
        : "+f"(c[0]), "+f"(c[1]), "+f"(c[2]), "+f"(c[3])
        : "r"(a[0]), "r"(a[1]), "r"(a[2]), "r"(a[3]), "r"(b0), "r"(b1));
}
__device__ __forceinline__ float ex2f(float x) {
    float r;
    asm("ex2.approx.ftz.f32 %0, %1;" : "=f"(r) : "f"(x));
    return r;
}
__device__ __forceinline__ uint32_t packh2(float a, float b) {
    __half2 h = __floats2half2_rn(a, b);
    return *(uint32_t*)&h;
}

// ---------------------------------------------------------------------------
// Convert x: fp32 -> fp16 into g_ah.
// ---------------------------------------------------------------------------
__global__ void __launch_bounds__(256) cvt_x(const float* __restrict__ in)
{
    size_t i = (size_t)blockIdx.x * 256 + threadIdx.x;   // float4 index
    float4 v = ((const float4*)in)[i];
    uint2 uh;
    __half2 h0 = __floats2half2_rn(v.x, v.y);
    __half2 h1 = __floats2half2_rn(v.z, v.w);
    uh.x = *(uint32_t*)&h0;
    uh.y = *(uint32_t*)&h1;
    ((uint2*)g_ah)[i] = uh;
}

// ---------------------------------------------------------------------------
// Transpose-convert all 4 weights: W[k][n] fp32 -> g_wh[z][n][k] fp16.
// ---------------------------------------------------------------------------
__global__ void __launch_bounds__(256) cvt_wt_all(const float* __restrict__ W0,
                                                  const float* __restrict__ W1,
                                                  const float* __restrict__ W2,
                                                  const float* __restrict__ W3)
{
    const float* Ws[4] = {W0, W1, W2, W3};
    const float* W = Ws[blockIdx.z];
    __half* dst = g_wh[blockIdx.z];
    __shared__ float t[32][33];
    const int n0 = blockIdx.x * 32, k0 = blockIdx.y * 32;
    const int tx = threadIdx.x & 31, ty = threadIdx.x >> 5;
    #pragma unroll
    for (int i = 0; i < 4; i++)
        t[ty + 8*i][tx] = W[(size_t)(k0 + ty + 8*i) * CC + n0 + tx];
    __syncthreads();
    #pragma unroll
    for (int i = 0; i < 4; i++) {
        int nn = ty + 8*i;
        dst[(size_t)(n0 + nn) * CC + k0 + tx] = __float2half(t[tx][nn]);
    }
}

// ---------------------------------------------------------------------------
// fp16 HGEMM:  Y[128x128 tile] = A @ Wh^T + bias
// BK=64 stages, 3-stage cp.async pipeline, 2 CTAs/SM (regs capped at 128).
// 256 threads = 8 warps (2m x 4n), warp tile 64x32.
// ---------------------------------------------------------------------------
template<bool QKV>
__global__ void __launch_bounds__(256, 2) gemm_fp16(const float* __restrict__ bias0,
                                                    const float* __restrict__ bias1,
                                                    const float* __restrict__ bias2,
                                                    float* __restrict__ Yext)
{
    extern __shared__ char sm[];
    const uint32_t smb = smem_u32(sm);
    const int tid  = threadIdx.x;
    const int wid  = tid >> 5;
    const int lane = tid & 31;
    const int warpM = wid >> 2;
    const int warpN = wid & 3;
    const int z = QKV ? (int)blockIdx.z : 3;

    const __half* __restrict__ Ah = g_ah;
    const __half* __restrict__ Bh = g_wh[z];
    const float* bias = QKV ? (z == 0 ? bias0 : z == 1 ? bias1 : bias2) : bias0;

    const int rowBase = blockIdx.y * BM;
    const int colBase = blockIdx.x * BN;

    const uint32_t aLane = (uint32_t)((lane & 15) * PADK + (lane >> 4) * 8) * 2;
    const uint32_t bLane = (uint32_t)(((lane & 7) + ((lane >> 4) & 1) * 8) * PADK
                                      + ((lane >> 3) & 1) * 8) * 2;

    float acc[4][4][4];
    #pragma unroll
    for (int i = 0; i < 4; i++)
        #pragma unroll
        for (int j = 0; j < 4; j++)
            #pragma unroll
            for (int r = 0; r < 4; r++) acc[i][j][r] = 0.f;

    auto stage_load = [&](int s, int buf) {
        const int kb = s * BK;
        const uint32_t base = smb + buf * STAGEB;
        #pragma unroll
        for (int i = 0; i < 4; i++) {
            const int idx = tid + i * 256;       // 0..1023
            const int row = idx >> 3, ch = idx & 7;
            const uint32_t d = base + (uint32_t)(row * ROWB + ch * 16);
            cpa16(d + AH_OFF, (const char*)(Ah + (size_t)(rowBase + row) * CC + kb) + ch * 16);
            cpa16(d + BH_OFF, (const char*)(Bh + (size_t)(colBase + row) * CC + kb) + ch * 16);
        }
    };

    const int NSTAGE = CC / BK;       // 16
    stage_load(0, 0); cpa_commit();
    stage_load(1, 1); cpa_commit();

    int buf = 0;
    for (int kt = 0; kt < NSTAGE; kt++) {
        if (kt + 2 < NSTAGE) {
            int nb = buf + 2; if (nb >= 3) nb -= 3;
            stage_load(kt + 2, nb);
            cpa_commit();
            cpa_wait<2>();
        } else if (kt + 1 < NSTAGE) {
            cpa_wait<1>();
        } else {
            cpa_wait<0>();
        }
        __syncthreads();

        const uint32_t aBase = smb + buf * STAGEB + AH_OFF
                             + (uint32_t)(warpM * 64 * ROWB) + aLane;
        const uint32_t bBase = smb + buf * STAGEB + BH_OFF
                             + (uint32_t)(warpN * 32 * ROWB) + bLane;

        #pragma unroll
        for (int kk = 0; kk < BK; kk += 16) {
            uint32_t ah[4][4], bh[2][4];
            #pragma unroll
            for (int mt = 0; mt < 4; mt++)
                ldsm4(ah[mt], aBase + (uint32_t)(mt * 16 * ROWB + kk * 2));
            #pragma unroll
            for (int np = 0; np < 2; np++)
                ldsm4(bh[np], bBase + (uint32_t)(np * 16 * ROWB + kk * 2));
            #pragma unroll
            for (int mt = 0; mt < 4; mt++)
                #pragma unroll
                for (int nt = 0; nt < 4; nt++) {
                    const int np = nt >> 1, s2 = (nt & 1) * 2;
                    mma16816h(acc[mt][nt], ah[mt], bh[np][s2], bh[np][s2 + 1]);
                }
        }
        __syncthreads();
        buf++; if (buf == 3) buf = 0;
    }

    #pragma unroll
    for (int mt = 0; mt < 4; mt++) {
        const int row = rowBase + warpM * 64 + mt * 16 + (lane >> 2);
        #pragma unroll
        for (int nt = 0; nt < 4; nt++) {
            const int col = colBase + warpN * 32 + nt * 8 + (lane & 3) * 2;
            const float2 b2 = *(const float2*)(bias + col);
            float v00 = acc[mt][nt][0] + b2.x, v01 = acc[mt][nt][1] + b2.y;
            float v10 = acc[mt][nt][2] + b2.x, v11 = acc[mt][nt][3] + b2.y;
            if constexpr (!QKV) {
                float2 o0 = {v00, v01}, o1 = {v10, v11};
                *(float2*)(Yext + (size_t)row * CC + col)       = o0;
                *(float2*)(Yext + (size_t)(row + 8) * CC + col) = o1;
            } else {
                __half* dst = (z == 0) ? g_qh : (z == 1) ? g_kh : g_vh;
                if (z == 0) { v00 *= SCQ; v01 *= SCQ; v10 *= SCQ; v11 *= SCQ; }
                *(__half2*)(dst + (size_t)row * CC + col)       = __floats2half2_rn(v00, v01);
                *(__half2*)(dst + (size_t)(row + 8) * CC + col) = __floats2half2_rn(v10, v11);
            }
        }
    }
}

// ---------------------------------------------------------------------------
// Tensor-core causal flash attention.  AQ=64, 4 warps, 5 CTAs/SM (regs<=102).
// Q via direct LDG, lane-local l, P-pack folded into PV loop (register relief).
// ---------------------------------------------------------------------------
__global__ void __launch_bounds__(128, 5) attn_tc()
{
    extern __shared__ char sm[];
    const uint32_t smb = smem_u32(sm);
    const int tid = threadIdx.x, wid = tid >> 5, lane = tid & 31;
    const int qb = (int)(gridDim.x - 1 - blockIdx.x) * AQ;   // heavy CTAs first
    const int h = blockIdx.y, b = blockIdx.z;
    const size_t rowOff = (size_t)(b * TT) * CC + h * DD;
    const int wr0 = qb + wid * 16;

    auto stageKV = [&](int t, int bufi) {
        int kb = t * AKV;
        #pragma unroll
        for (int i = 0; i < 8; i++) {
            int idx = tid + i * 128;             // 0..1023
            int mv = idx >> 9, r = (idx >> 3) & 63, ch = idx & 7;
            const __half* src = (mv ? g_vh : g_kh) + rowOff + (size_t)(kb + r) * CC + ch * 8;
            cpa16(smb + (mv ? SV0 : SK0) + (uint32_t)(bufi * (64 * AST) + r * AST + ch * 16), src);
        }
    };
    stageKV(0, 0);
    cpa_commit();

    // ---- Q fragments via direct LDG (canonical m16n8k16 A-frag layout) ----
    uint32_t qf[4][4];
    {
        const __half* q0 = g_qh + rowOff + (size_t)(wr0 + (lane >> 2)) * CC + (lane & 3) * 2;
        #pragma unroll
        for (int ks = 0; ks < 4; ks++) {
            qf[ks][0] = *(const uint32_t*)(q0 + ks * 16);
            qf[ks][1] = *(const uint32_t*)(q0 + 8 * CC + ks * 16);
            qf[ks][2] = *(const uint32_t*)(q0 + ks * 16 + 8);
            qf[ks][3] = *(const uint32_t*)(q0 + 8 * CC + ks * 16 + 8);
        }
    }

    cpa_wait<0>();
    __syncthreads();

    float O[8][4];
    #pragma unroll
    for (int i = 0; i < 8; i++)
        #pragma unroll
        for (int j = 0; j < 4; j++) O[i][j] = 0.f;
    float m0 = -1e30f, m1 = -1e30f, l0 = 0.f, l1 = 0.f;   // l: lane-local partials

    const int ntiles = qb / AKV + 1;
    const uint32_t klane = (uint32_t)(((lane & 7) + ((lane >> 4) & 1) * 8) * AST
                                      + ((lane >> 3) & 1) * 16);
    const uint32_t vlane = (uint32_t)(((lane & 7) + ((lane >> 3) & 1) * 8) * AST
                                      + ((lane >> 4) & 1) * 16);

    for (int t = 0; t < ntiles; t++) {
        const int bufi = t & 1;
        if (t + 1 < ntiles) {
            stageKV(t + 1, bufi ^ 1);
            cpa_commit();
            cpa_wait<1>();
        } else {
            cpa_wait<0>();
        }
        __syncthreads();

        const int kb = t * AKV;

        // ---- scores S = Q . K^T ----
        float S[8][4];
        #pragma unroll
        for (int i = 0; i < 8; i++)
            #pragma unroll
            for (int j = 0; j < 4; j++) S[i][j] = 0.f;

        const uint32_t kbase = smb + SK0 + (uint32_t)(bufi * (64 * AST)) + klane;
        #pragma unroll
        for (int nn = 0; nn < 4; nn++)
            #pragma unroll
            for (int ks = 0; ks < 4; ks++) {
                uint32_t kf[4];
                ldsm4(kf, kbase + (uint32_t)(nn * 16 * AST + ks * 32));
                mma16816h(S[2*nn],   qf[ks], kf[0], kf[1]);
                mma16816h(S[2*nn+1], qf[ks], kf[2], kf[3]);
            }

        // ---- causal mask (diagonal tile only) ----
        if (kb + 63 > wr0) {
            const int r0 = wr0 + (lane >> 2), r1 = r0 + 8;
            #pragma unroll
            for (int sf = 0; sf < 8; sf++) {
                const int c = kb + sf * 8 + (lane & 3) * 2;
                if (c     > r0) S[sf][0] = -1e30f;
                if (c + 1 > r0) S[sf][1] = -1e30f;
                if (c     > r1) S[sf][2] = -1e30f;
                if (c + 1 > r1) S[sf][3] = -1e30f;
            }
        }

        // ---- online softmax: row max (only the max needs cross-lane) ----
        float mx0 = -1e30f, mx1 = -1e30f;
        #pragma unroll
        for (int sf = 0; sf < 8; sf++) {
            mx0 = fmaxf(mx0, fmaxf(S[sf][0], S[sf][1]));
            mx1 = fmaxf(mx1, fmaxf(S[sf][2], S[sf][3]));
        }
        mx0 = fmaxf(mx0, __shfl_xor_sync(0xffffffffu, mx0, 1));
        mx0 = fmaxf(mx0, __shfl_xor_sync(0xffffffffu, mx0, 2));
        mx1 = fmaxf(mx1, __shfl_xor_sync(0xffffffffu, mx1, 1));
        mx1 = fmaxf(mx1, __shfl_xor_sync(0xffffffffu, mx1, 2));
        const float nm0 = fmaxf(m0, mx0), nm1 = fmaxf(m1, mx1);
        const float corr0 = ex2f(m0 - nm0), corr1 = ex2f(m1 - nm1);
        m0 = nm0; m1 = nm1;

        // ---- exp + lane-local partial sums (no shuffles here) ----
        float sum0 = 0.f, sum1 = 0.f;
        #pragma unroll
        for (int sf = 0; sf < 8; sf++) {
            S[sf][0] = ex2f(S[sf][0] - nm0);
            S[sf][1] = ex2f(S[sf][1] - nm0);
            S[sf][2] = ex2f(S[sf][2] - nm1);
            S[sf][3] = ex2f(S[sf][3] - nm1);
            sum0 += S[sf][0] + S[sf][1];
            sum1 += S[sf][2] + S[sf][3];
        }
        l0 = l0 * corr0 + sum0;
        l1 = l1 * corr1 + sum1;

        #pragma unroll
        for (int sf = 0; sf < 8; sf++) {
            O[sf][0] *= corr0; O[sf][1] *= corr0;
            O[sf][2] *= corr1; O[sf][3] *= corr1;
        }

        // ---- O += P . V, with P-pack folded per-j (S dies progressively) ----
        const uint32_t vbase = smb + SV0 + (uint32_t)(bufi * (64 * AST)) + vlane;
        #pragma unroll
        for (int j = 0; j < 4; j++) {
            uint32_t pa[4];
            pa[0] = packh2(S[2*j][0],   S[2*j][1]);
            pa[1] = packh2(S[2*j][2],   S[2*j][3]);
            pa[2] = packh2(S[2*j+1][0], S[2*j+1][1]);
            pa[3] = packh2(S[2*j+1][2], S[2*j+1][3]);
            #pragma unroll
            for (int dd = 0; dd < 4; dd++) {
                uint32_t vf[4];
                ldsm4t(vf, vbase + (uint32_t)(j * 16 * AST + dd * 32));
                mma16816h(O[2*dd],   pa, vf[0], vf[1]);
                mma16816h(O[2*dd+1], pa, vf[2], vf[3]);
            }
        }

        __syncthreads();
    }

    // ---- cross-lane l reduction, once ----
    l0 += __shfl_xor_sync(0xffffffffu, l0, 1);
    l0 += __shfl_xor_sync(0xffffffffu, l0, 2);
    l1 += __shfl_xor_sync(0xffffffffu, l1, 1);
    l1 += __shfl_xor_sync(0xffffffffu, l1, 2);

    // ---- epilogue: normalize, convert fp16, store into g_ah ----
    const float inv0 = 1.f / l0, inv1 = 1.f / l1;
    const int row0 = qb + wid * 16 + (lane >> 2);
    #pragma unroll
    for (int sf = 0; sf < 8; sf++) {
        const int col = h * DD + sf * 8 + (lane & 3) * 2;
        *(__half2*)(g_ah + (size_t)(b * TT + row0) * CC + col) =
            __floats2half2_rn(O[sf][0] * inv0, O[sf][1] * inv0);
        *(__half2*)(g_ah + (size_t)(b * TT + row0 + 8) * CC + col) =
            __floats2half2_rn(O[sf][2] * inv1, O[sf][3] * inv1);
    }
}

// ---------------------------------------------------------------------------
// Launch sequence
// ---------------------------------------------------------------------------
extern "C" void kernel_launch(void* const* d_in, const int* in_sizes, int n_in,
                              void* d_out, int out_size)
{
    const float* x  = (const float*)d_in[0];
    const float* Wq = (const float*)d_in[1];
    const float* bq = (const float*)d_in[2];
    const float* Wk = (const float*)d_in[3];
    const float* bk = (const float*)d_in[4];
    const float* Wv = (const float*)d_in[5];
    const float* bv = (const float*)d_in[6];
    const float* Wo = (const float*)d_in[7];
    const float* bo = (const float*)d_in[8];
    float* out = (float*)d_out;

    cudaFuncSetAttribute(gemm_fp16<true>,  cudaFuncAttributeMaxDynamicSharedMemorySize, GSMEM_TOTAL);
    cudaFuncSetAttribute(gemm_fp16<false>, cudaFuncAttributeMaxDynamicSharedMemorySize, GSMEM_TOTAL);
    cudaFuncSetAttribute(attn_tc,          cudaFuncAttributeMaxDynamicSharedMemorySize, ASMEM);

    const dim3 gcv(MM * CC / 4 / 256);
    const dim3 gtr(CC / 32, CC / 32, 4);
    const dim3 gqkv(CC / BN, MM / BM, 3);
    const dim3 go(CC / BN, MM / BM);

    cvt_x<<<gcv, 256>>>(x);
    cvt_wt_all<<<gtr, 256>>>(Wq, Wk, Wv, Wo);

    gemm_fp16<true><<<gqkv, 256, GSMEM_TOTAL>>>(bq, bk, bv, nullptr);

    const dim3 ga(TT / AQ, HH, BB);
    attn_tc<<<ga, 128, ASMEM>>>();

    gemm_fp16<false><<<go, 256, GSMEM_TOTAL>>>(bo, nullptr, nullptr, out);
}

// round 15
// speedup vs baseline: 1.0372x; 1.0372x over previous
#include <cuda_runtime.h>
#include <cuda_fp16.h>
#include <cstdint>

#define BB 2
#define TT 2048
#define CC 1024
#define HH 16
#define DD 64
#define MM (BB*TT)

// ---- projection GEMM tiling ----
#define BM 128
#define BN 128
#define BK 64
#define PADK 72                 // smem row stride in halves (144 B), conflict-free
#define ROWB (PADK*2)           // 144 bytes
#define AH_OFF 0
#define BH_OFF (128*ROWB)       // 18432
#define STAGEB (2*128*ROWB)     // 36864
#define GSMEM_TOTAL (3*STAGEB)  // 110592 B  (x2 CTAs <= carveout)

// ---- attention tiling: AQ=64, 4 warps, 4 CTAs/SM; Q direct-LDG ----
#define AQ  64
#define AKV 64
#define AST 144
#define SK0 0
#define SV0 (2*64*AST)          // 18432 (after 2 K stages)
#define ASMEM (4*64*AST)        // 36864  (x4 CTAs = 147456)

#define SCQ (0.125f * 1.44269504088896340736f)   // 1/sqrt(D) * log2(e)

// ---------------------------------------------------------------------------
// Scratch (allocation-free device globals) — all fp16
// ---------------------------------------------------------------------------
__device__ __align__(256) __half g_qh[MM*CC];    // Q * 0.125*log2e
__device__ __align__(256) __half g_kh[MM*CC];
__device__ __align__(256) __half g_vh[MM*CC];
__device__ __align__(256) __half g_ah[MM*CC];    // A operand (x, later att out)
__device__ __align__(256) __half g_wh[4][CC*CC]; // W transposed [n][k], fp16

// ---------------------------------------------------------------------------
// PTX helpers (baseline sm_80+ features only)
// ---------------------------------------------------------------------------
__device__ __forceinline__ uint32_t smem_u32(const void* p) {
    uint32_t a;
    asm("{ .reg .u64 t; cvta.to.shared.u64 t, %1; cvt.u32.u64 %0, t; }" : "=r"(a) : "l"(p));
    return a;
}
__device__ __forceinline__ void cpa16(uint32_t dst, const void* src) {
    asm volatile("cp.async.cg.shared.global [%0], [%1], 16;" :: "r"(dst), "l"(src));
}
__device__ __forceinline__ void cpa_commit() {
    asm volatile("cp.async.commit_group;" ::: "memory");
}
template<int N>
__device__ __forceinline__ void cpa_wait() {
    asm volatile("cp.async.wait_group %0;" :: "n"(N) : "memory");
}
__device__ __forceinline__ void ldsm4(uint32_t* r, uint32_t addr) {
    asm volatile("ldmatrix.sync.aligned.m8n8.x4.shared.b16 {%0,%1,%2,%3}, [%4];"
        : "=r"(r[0]), "=r"(r[1]), "=r"(r[2]), "=r"(r[3]) : "r"(addr));
}
__device__ __forceinline__ void ldsm4t(uint32_t* r, uint32_t addr) {
    asm volatile("ldmatrix.sync.aligned.m8n8.x4.trans.shared.b16 {%0,%1,%2,%3}, [%4];"
        : "=r"(r[0]), "=r"(r[1]), "=r"(r[2]), "=r"(r[3]) : "r"(addr));
}
__device__ __forceinline__ void mma16816h(float* c, const uint32_t* a,
                                          uint32_t b0, uint32_t b1) {
    asm volatile("mma.sync.aligned.m16n8k16.row.col.f32.f16.f16.f32 "
        "{%0,%1,%2,%3}, {%4,%5,%6,%7}, {%8,%9}, {%0,%1,%2,%3};"
        : "+f"(c[0]), "+f"(c[1]), "+f"(c[2]), "+f"(c[3])
        : "r"(a[0]), "r"(a[1]), "r"(a[2]), "r"(a[3]), "r"(b0), "r"(b1));
}
__device__ __forceinline__ float ex2f(float x) {
    float r;
    asm("ex2.approx.ftz.f32 %0, %1;" : "=f"(r) : "f"(x));
    return r;
}
__device__ __forceinline__ uint32_t packh2(float a, float b) {
    __half2 h = __floats2half2_rn(a, b);
    return *(uint32_t*)&h;
}

// ---------------------------------------------------------------------------
// Fused conversions: z=0..3 transpose W[z] fp32->fp16 [n][k]; z=4 converts x.
// ---------------------------------------------------------------------------
__global__ void __launch_bounds__(256) cvt_all(const float* __restrict__ x,
                                               const float* __restrict__ W0,
                                               const float* __restrict__ W1,
                                               const float* __restrict__ W2,
                                               const float* __restrict__ W3)
{
    const int z = blockIdx.z;
    if (z < 4) {
        const float* Ws[4] = {W0, W1, W2, W3};
        const float* W = Ws[z];
        __half* dst = g_wh[z];
        __shared__ float t[32][33];
        const int n0 = blockIdx.x * 32, k0 = blockIdx.y * 32;
        const int tx = threadIdx.x & 31, ty = threadIdx.x >> 5;
        #pragma unroll
        for (int i = 0; i < 4; i++)
            t[ty + 8*i][tx] = W[(size_t)(k0 + ty + 8*i) * CC + n0 + tx];
        __syncthreads();
        #pragma unroll
        for (int i = 0; i < 4; i++) {
            int nn = ty + 8*i;
            dst[(size_t)(n0 + nn) * CC + k0 + tx] = __float2half(t[tx][nn]);
        }
    } else {
        // x: MM*CC floats = 1M float4; 1024 blocks (32x32) x 256 thr x 4 iters
        const size_t base = (size_t)(blockIdx.y * 32 + blockIdx.x) * 1024;
        #pragma unroll
        for (int k = 0; k < 4; k++) {
            const size_t i = base + threadIdx.x + k * 256;
            float4 v = ((const float4*)x)[i];
            uint2 uh;
            __half2 h0 = __floats2half2_rn(v.x, v.y);
            __half2 h1 = __floats2half2_rn(v.z, v.w);
            uh.x = *(uint32_t*)&h0;
            uh.y = *(uint32_t*)&h1;
            ((uint2*)g_ah)[i] = uh;
        }
    }
}

// ---------------------------------------------------------------------------
// fp16 HGEMM:  Y[128x128 tile] = A @ Wh^T + bias
// BK=64 stages, 3-stage cp.async pipeline, 2 CTAs/SM (regs capped at 128).
// 256 threads = 8 warps (2m x 4n), warp tile 64x32.
// ---------------------------------------------------------------------------
template<bool QKV>
__global__ void __launch_bounds__(256, 2) gemm_fp16(const float* __restrict__ bias0,
                                                    const float* __restrict__ bias1,
                                                    const float* __restrict__ bias2,
                                                    float* __restrict__ Yext)
{
    extern __shared__ char sm[];
    const uint32_t smb = smem_u32(sm);
    const int tid  = threadIdx.x;
    const int wid  = tid >> 5;
    const int lane = tid & 31;
    const int warpM = wid >> 2;
    const int warpN = wid & 3;
    const int z = QKV ? (int)blockIdx.z : 3;

    const __half* __restrict__ Ah = g_ah;
    const __half* __restrict__ Bh = g_wh[z];
    const float* bias = QKV ? (z == 0 ? bias0 : z == 1 ? bias1 : bias2) : bias0;

    const int rowBase = blockIdx.y * BM;
    const int colBase = blockIdx.x * BN;

    const uint32_t aLane = (uint32_t)((lane & 15) * PADK + (lane >> 4) * 8) * 2;
    const uint32_t bLane = (uint32_t)(((lane & 7) + ((lane >> 4) & 1) * 8) * PADK
                                      + ((lane >> 3) & 1) * 8) * 2;

    float acc[4][4][4];
    #pragma unroll
    for (int i = 0; i < 4; i++)
        #pragma unroll
        for (int j = 0; j < 4; j++)
            #pragma unroll
            for (int r = 0; r < 4; r++) acc[i][j][r] = 0.f;

    auto stage_load = [&](int s, int buf) {
        const int kb = s * BK;
        const uint32_t base = smb + buf * STAGEB;
        #pragma unroll
        for (int i = 0; i < 4; i++) {
            const int idx = tid + i * 256;       // 0..1023
            const int row = idx >> 3, ch = idx & 7;
            const uint32_t d = base + (uint32_t)(row * ROWB + ch * 16);
            cpa16(d + AH_OFF, (const char*)(Ah + (size_t)(rowBase + row) * CC + kb) + ch * 16);
            cpa16(d + BH_OFF, (const char*)(Bh + (size_t)(colBase + row) * CC + kb) + ch * 16);
        }
    };

    const int NSTAGE = CC / BK;       // 16
    stage_load(0, 0); cpa_commit();
    stage_load(1, 1); cpa_commit();

    int buf = 0;
    for (int kt = 0; kt < NSTAGE; kt++) {
        if (kt + 2 < NSTAGE) {
            int nb = buf + 2; if (nb >= 3) nb -= 3;
            stage_load(kt + 2, nb);
            cpa_commit();
            cpa_wait<2>();
        } else if (kt + 1 < NSTAGE) {
            cpa_wait<1>();
        } else {
            cpa_wait<0>();
        }
        __syncthreads();

        const uint32_t aBase = smb + buf * STAGEB + AH_OFF
                             + (uint32_t)(warpM * 64 * ROWB) + aLane;
        const uint32_t bBase = smb + buf * STAGEB + BH_OFF
                             + (uint32_t)(warpN * 32 * ROWB) + bLane;

        #pragma unroll
        for (int kk = 0; kk < BK; kk += 16) {
            uint32_t ah[4][4], bh[2][4];
            #pragma unroll
            for (int mt = 0; mt < 4; mt++)
                ldsm4(ah[mt], aBase + (uint32_t)(mt * 16 * ROWB + kk * 2));
            #pragma unroll
            for (int np = 0; np < 2; np++)
                ldsm4(bh[np], bBase + (uint32_t)(np * 16 * ROWB + kk * 2));
            #pragma unroll
            for (int mt = 0; mt < 4; mt++)
                #pragma unroll
                for (int nt = 0; nt < 4; nt++) {
                    const int np = nt >> 1, s2 = (nt & 1) * 2;
                    mma16816h(acc[mt][nt], ah[mt], bh[np][s2], bh[np][s2 + 1]);
                }
        }
        __syncthreads();
        buf++; if (buf == 3) buf = 0;
    }

    #pragma unroll
    for (int mt = 0; mt < 4; mt++) {
        const int row = rowBase + warpM * 64 + mt * 16 + (lane >> 2);
        #pragma unroll
        for (int nt = 0; nt < 4; nt++) {
            const int col = colBase + warpN * 32 + nt * 8 + (lane & 3) * 2;
            const float2 b2 = *(const float2*)(bias + col);
            float v00 = acc[mt][nt][0] + b2.x, v01 = acc[mt][nt][1] + b2.y;
            float v10 = acc[mt][nt][2] + b2.x, v11 = acc[mt][nt][3] + b2.y;
            if constexpr (!QKV) {
                float2 o0 = {v00, v01}, o1 = {v10, v11};
                *(float2*)(Yext + (size_t)row * CC + col)       = o0;
                *(float2*)(Yext + (size_t)(row + 8) * CC + col) = o1;
            } else {
                __half* dst = (z == 0) ? g_qh : (z == 1) ? g_kh : g_vh;
                if (z == 0) { v00 *= SCQ; v01 *= SCQ; v10 *= SCQ; v11 *= SCQ; }
                *(__half2*)(dst + (size_t)row * CC + col)       = __floats2half2_rn(v00, v01);
                *(__half2*)(dst + (size_t)(row + 8) * CC + col) = __floats2half2_rn(v10, v11);
            }
        }
    }
}

// ---------------------------------------------------------------------------
// Tensor-core causal flash attention (R13 structure: AQ=64, 4 warps,
// 4 CTAs/SM, Q direct-LDG, lane-local l) + diagonal-tile work skipping:
// in the last tile, warp w only needs key groups nn <= w (rest fully masked).
// ---------------------------------------------------------------------------
__global__ void __launch_bounds__(128, 4) attn_tc()
{
    extern __shared__ char sm[];
    const uint32_t smb = smem_u32(sm);
    const int tid = threadIdx.x, wid = tid >> 5, lane = tid & 31;
    const int qb = (int)(gridDim.x - 1 - blockIdx.x) * AQ;   // heavy CTAs first
    const int h = blockIdx.y, b = blockIdx.z;
    const size_t rowOff = (size_t)(b * TT) * CC + h * DD;
    const int wr0 = qb + wid * 16;

    auto stageKV = [&](int t, int bufi) {
        int kb = t * AKV;
        #pragma unroll
        for (int i = 0; i < 8; i++) {
            int idx = tid + i * 128;             // 0..1023
            int mv = idx >> 9, r = (idx >> 3) & 63, ch = idx & 7;
            const __half* src = (mv ? g_vh : g_kh) + rowOff + (size_t)(kb + r) * CC + ch * 8;
            cpa16(smb + (mv ? SV0 : SK0) + (uint32_t)(bufi * (64 * AST) + r * AST + ch * 16), src);
        }
    };
    stageKV(0, 0);
    cpa_commit();

    // ---- Q fragments via direct LDG (canonical m16n8k16 A-frag layout) ----
    uint32_t qf[4][4];
    {
        const __half* q0 = g_qh + rowOff + (size_t)(wr0 + (lane >> 2)) * CC + (lane & 3) * 2;
        #pragma unroll
        for (int ks = 0; ks < 4; ks++) {
            qf[ks][0] = *(const uint32_t*)(q0 + ks * 16);
            qf[ks][1] = *(const uint32_t*)(q0 + 8 * CC + ks * 16);
            qf[ks][2] = *(const uint32_t*)(q0 + ks * 16 + 8);
            qf[ks][3] = *(const uint32_t*)(q0 + 8 * CC + ks * 16 + 8);
        }
    }

    cpa_wait<0>();
    __syncthreads();

    float O[8][4];
    #pragma unroll
    for (int i = 0; i < 8; i++)
        #pragma unroll
        for (int j = 0; j < 4; j++) O[i][j] = 0.f;
    float m0 = -1e30f, m1 = -1e30f, l0 = 0.f, l1 = 0.f;   // l: lane-local partials

    const int ntiles = qb / AKV + 1;
    const uint32_t klane = (uint32_t)(((lane & 7) + ((lane >> 4) & 1) * 8) * AST
                                      + ((lane >> 3) & 1) * 16);
    const uint32_t vlane = (uint32_t)(((lane & 7) + ((lane >> 3) & 1) * 8) * AST
                                      + ((lane >> 4) & 1) * 16);

    for (int t = 0; t < ntiles; t++) {
        const int bufi = t & 1;
        if (t + 1 < ntiles) {
            stageKV(t + 1, bufi ^ 1);
            cpa_commit();
            cpa_wait<1>();
        } else {
            cpa_wait<0>();
        }
        __syncthreads();

        const int kb = t * AKV;
        // Diagonal tile (kb == qb): warp w only touches key groups nn <= w;
        // groups nn > w are fully masked (their contribution is exactly 0).
        const int nnmax = (kb == qb) ? (wid + 1) : 4;

        // ---- scores S = Q . K^T ----
        float S[8][4];
        #pragma unroll
        for (int i = 0; i < 8; i++)
            #pragma unroll
            for (int j = 0; j < 4; j++) S[i][j] = 0.f;

        const uint32_t kbase = smb + SK0 + (uint32_t)(bufi * (64 * AST)) + klane;
        #pragma unroll
        for (int nn = 0; nn < 4; nn++) {
            if (nn < nnmax) {
                #pragma unroll
                for (int ks = 0; ks < 4; ks++) {
                    uint32_t kf[4];
                    ldsm4(kf, kbase + (uint32_t)(nn * 16 * AST + ks * 32));
                    mma16816h(S[2*nn],   qf[ks], kf[0], kf[1]);
                    mma16816h(S[2*nn+1], qf[ks], kf[2], kf[3]);
                }
            }
        }

        // ---- causal mask (diagonal tile only; also forces skipped groups
        //      to -1e30 so softmax sees them as empty) ----
        if (kb + 63 > wr0) {
            const int r0 = wr0 + (lane >> 2), r1 = r0 + 8;
            #pragma unroll
            for (int sf = 0; sf < 8; sf++) {
                const int c = kb + sf * 8 + (lane & 3) * 2;
                if (c     > r0) S[sf][0] = -1e30f;
                if (c + 1 > r0) S[sf][1] = -1e30f;
                if (c     > r1) S[sf][2] = -1e30f;
                if (c + 1 > r1) S[sf][3] = -1e30f;
            }
        }

        // ---- online softmax: row max (only the max needs cross-lane) ----
        float mx0 = -1e30f, mx1 = -1e30f;
        #pragma unroll
        for (int sf = 0; sf < 8; sf++) {
            mx0 = fmaxf(mx0, fmaxf(S[sf][0], S[sf][1]));
            mx1 = fmaxf(mx1, fmaxf(S[sf][2], S[sf][3]));
        }
        mx0 = fmaxf(mx0, __shfl_xor_sync(0xffffffffu, mx0, 1));
        mx0 = fmaxf(mx0, __shfl_xor_sync(0xffffffffu, mx0, 2));
        mx1 = fmaxf(mx1, __shfl_xor_sync(0xffffffffu, mx1, 1));
        mx1 = fmaxf(mx1, __shfl_xor_sync(0xffffffffu, mx1, 2));
        const float nm0 = fmaxf(m0, mx0), nm1 = fmaxf(m1, mx1);
        const float corr0 = ex2f(m0 - nm0), corr1 = ex2f(m1 - nm1);
        m0 = nm0; m1 = nm1;

        // ---- exp + lane-local partial sums (no shuffles here) ----
        float sum0 = 0.f, sum1 = 0.f;
        #pragma unroll
        for (int sf = 0; sf < 8; sf++) {
            S[sf][0] = ex2f(S[sf][0] - nm0);
            S[sf][1] = ex2f(S[sf][1] - nm0);
            S[sf][2] = ex2f(S[sf][2] - nm1);
            S[sf][3] = ex2f(S[sf][3] - nm1);
            sum0 += S[sf][0] + S[sf][1];
            sum1 += S[sf][2] + S[sf][3];
        }
        l0 = l0 * corr0 + sum0;
        l1 = l1 * corr1 + sum1;

        #pragma unroll
        for (int sf = 0; sf < 8; sf++) {
            O[sf][0] *= corr0; O[sf][1] *= corr0;
            O[sf][2] *= corr1; O[sf][3] *= corr1;
        }

        // ---- pack P into fp16 A-fragments ----
        uint32_t pa[4][4];
        #pragma unroll
        for (int j = 0; j < 4; j++) {
            #pragma unroll
            for (int q = 0; q < 4; q++) {
                const int sf = 2 * j + (q >> 1);
                const int e  = (q & 1) * 2;
                pa[j][q] = packh2(S[sf][e], S[sf][e + 1]);
            }
        }

        // ---- O += P . V (skip key groups that are fully masked) ----
        const uint32_t vbase = smb + SV0 + (uint32_t)(bufi * (64 * AST)) + vlane;
        #pragma unroll
        for (int dd = 0; dd < 4; dd++)
            #pragma unroll
            for (int j = 0; j < 4; j++) {
                if (j < nnmax) {
                    uint32_t vf[4];
                    ldsm4t(vf, vbase + (uint32_t)(j * 16 * AST + dd * 32));
                    mma16816h(O[2*dd],   pa[j], vf[0], vf[1]);
                    mma16816h(O[2*dd+1], pa[j], vf[2], vf[3]);
                }
            }

        __syncthreads();
    }

    // ---- cross-lane l reduction, once ----
    l0 += __shfl_xor_sync(0xffffffffu, l0, 1);
    l0 += __shfl_xor_sync(0xffffffffu, l0, 2);
    l1 += __shfl_xor_sync(0xffffffffu, l1, 1);
    l1 += __shfl_xor_sync(0xffffffffu, l1, 2);

    // ---- epilogue: normalize, convert fp16, store into g_ah ----
    const float inv0 = 1.f / l0, inv1 = 1.f / l1;
    const int row0 = qb + wid * 16 + (lane >> 2);
    #pragma unroll
    for (int sf = 0; sf < 8; sf++) {
        const int col = h * DD + sf * 8 + (lane & 3) * 2;
        *(__half2*)(g_ah + (size_t)(b * TT + row0) * CC + col) =
            __floats2half2_rn(O[sf][0] * inv0, O[sf][1] * inv0);
        *(__half2*)(g_ah + (size_t)(b * TT + row0 + 8) * CC + col) =
            __floats2half2_rn(O[sf][2] * inv1, O[sf][3] * inv1);
    }
}

// ---------------------------------------------------------------------------
// Launch sequence
// ---------------------------------------------------------------------------
extern "C" void kernel_launch(void* const* d_in, const int* in_sizes, int n_in,
                              void* d_out, int out_size)
{
    const float* x  = (const float*)d_in[0];
    const float* Wq = (const float*)d_in[1];
    const float* bq = (const float*)d_in[2];
    const float* Wk = (const float*)d_in[3];
    const float* bk = (const float*)d_in[4];
    const float* Wv = (const float*)d_in[5];
    const float* bv = (const float*)d_in[6];
    const float* Wo = (const float*)d_in[7];
    const float* bo = (const float*)d_in[8];
    float* out = (float*)d_out;

    cudaFuncSetAttribute(gemm_fp16<true>,  cudaFuncAttributeMaxDynamicSharedMemorySize, GSMEM_TOTAL);
    cudaFuncSetAttribute(gemm_fp16<false>, cudaFuncAttributeMaxDynamicSharedMemorySize, GSMEM_TOTAL);
    cudaFuncSetAttribute(attn_tc,          cudaFuncAttributeMaxDynamicSharedMemorySize, ASMEM);

    const dim3 gcv(CC / 32, CC / 32, 5);       // fused weight-transpose + x-convert
    const dim3 gqkv(CC / BN, MM / BM, 3);
    const dim3 go(CC / BN, MM / BM);

    cvt_all<<<gcv, 256>>>(x, Wq, Wk, Wv, Wo);

    gemm_fp16<true><<<gqkv, 256, GSMEM_TOTAL>>>(bq, bk, bv, nullptr);

    const dim3 ga(TT / AQ, HH, BB);
    attn_tc<<<ga, 128, ASMEM>>>();

    gemm_fp16<false><<<go, 256, GSMEM_TOTAL>>>(bo, nullptr, nullptr, out);
}

// round 16
// speedup vs baseline: 1.0904x; 1.0513x over previous
#include <cuda_runtime.h>
#include <cuda_fp16.h>
#include <cstdint>

#define BB 2
#define TT 2048
#define CC 1024
#define HH 16
#define DD 64
#define MM (BB*TT)

// ---- projection GEMM tiling ----
#define BM 128
#define BN 128
#define BK 64
#define PADK 72                 // smem row stride in halves (144 B), conflict-free
#define ROWB (PADK*2)           // 144 bytes
#define AH_OFF 0
#define BH_OFF (128*ROWB)       // 18432
#define STAGEB (2*128*ROWB)     // 36864
#define GSMEM_TOTAL (3*STAGEB)  // 110592 B  (x2 CTAs <= carveout)

// ---- attention tiling: AQ=64, 4 warps, 4 CTAs/SM; Q direct-LDG ----
// 3-buffer KV ring, ONE __syncthreads per tile.
#define AQ  64
#define AKV 64
#define AST 144
#define KVHALF (64*AST)         // 9216: V offset within a buffer
#define PAIRB (2*64*AST)        // 18432 per ring buffer (K+V)
#define ASMEM (3*PAIRB)         // 55296  (x4 CTAs = 221184 <= carveout)

#define SCQ (0.125f * 1.44269504088896340736f)   // 1/sqrt(D) * log2(e)

// ---------------------------------------------------------------------------
// Scratch (allocation-free device globals) — all fp16
// ---------------------------------------------------------------------------
__device__ __align__(256) __half g_qh[MM*CC];    // Q * 0.125*log2e
__device__ __align__(256) __half g_kh[MM*CC];
__device__ __align__(256) __half g_vh[MM*CC];
__device__ __align__(256) __half g_ah[MM*CC];    // A operand (x, later att out)
__device__ __align__(256) __half g_wh[4][CC*CC]; // W transposed [n][k], fp16

// ---------------------------------------------------------------------------
// PTX helpers (baseline sm_80+ features only)
// ---------------------------------------------------------------------------
__device__ __forceinline__ uint32_t smem_u32(const void* p) {
    uint32_t a;
    asm("{ .reg .u64 t; cvta.to.shared.u64 t, %1; cvt.u32.u64 %0, t; }" : "=r"(a) : "l"(p));
    return a;
}
__device__ __forceinline__ void cpa16(uint32_t dst, const void* src) {
    asm volatile("cp.async.cg.shared.global [%0], [%1], 16;" :: "r"(dst), "l"(src));
}
__device__ __forceinline__ void cpa_commit() {
    asm volatile("cp.async.commit_group;" ::: "memory");
}
template<int N>
__device__ __forceinline__ void cpa_wait() {
    asm volatile("cp.async.wait_group %0;" :: "n"(N) : "memory");
}
__device__ __forceinline__ void ldsm4(uint32_t* r, uint32_t addr) {
    asm volatile("ldmatrix.sync.aligned.m8n8.x4.shared.b16 {%0,%1,%2,%3}, [%4];"
        : "=r"(r[0]), "=r"(r[1]), "=r"(r[2]), "=r"(r[3]) : "r"(addr));
}
__device__ __forceinline__ void ldsm4t(uint32_t* r, uint32_t addr) {
    asm volatile("ldmatrix.sync.aligned.m8n8.x4.trans.shared.b16 {%0,%1,%2,%3}, [%4];"
        : "=r"(r[0]), "=r"(r[1]), "=r"(r[2]), "=r"(r[3]) : "r"(addr));
}
__device__ __forceinline__ void mma16816h(float* c, const uint32_t* a,
                                          uint32_t b0, uint32_t b1) {
    asm volatile("mma.sync.aligned.m16n8k16.row.col.f32.f16.f16.f32 "
        "{%0,%1,%2,%3}, {%4,%5,%6,%7}, {%8,%9}, {%0,%1,%2,%3};"
        : "+f"(c[0]), "+f"(c[1]), "+f"(c[2]), "+f"(c[3])
        : "r"(a[0]), "r"(a[1]), "r"(a[2]), "r"(a[3]), "r"(b0), "r"(b1));
}
__device__ __forceinline__ float ex2f(float x) {
    float r;
    asm("ex2.approx.ftz.f32 %0, %1;" : "=f"(r) : "f"(x));
    return r;
}
__device__ __forceinline__ uint32_t packh2(float a, float b) {
    __half2 h = __floats2half2_rn(a, b);
    return *(uint32_t*)&h;
}

// ---------------------------------------------------------------------------
// Fused conversions: z=0..3 transpose W[z] fp32->fp16 [n][k]; z=4 converts x.
// ---------------------------------------------------------------------------
__global__ void __launch_bounds__(256) cvt_all(const float* __restrict__ x,
                                               const float* __restrict__ W0,
                                               const float* __restrict__ W1,
                                               const float* __restrict__ W2,
                                               const float* __restrict__ W3)
{
    const int z = blockIdx.z;
    if (z < 4) {
        const float* Ws[4] = {W0, W1, W2, W3};
        const float* W = Ws[z];
        __half* dst = g_wh[z];
        __shared__ float t[32][33];
        const int n0 = blockIdx.x * 32, k0 = blockIdx.y * 32;
        const int tx = threadIdx.x & 31, ty = threadIdx.x >> 5;
        #pragma unroll
        for (int i = 0; i < 4; i++)
            t[ty + 8*i][tx] = W[(size_t)(k0 + ty + 8*i) * CC + n0 + tx];
        __syncthreads();
        #pragma unroll
        for (int i = 0; i < 4; i++) {
            int nn = ty + 8*i;
            dst[(size_t)(n0 + nn) * CC + k0 + tx] = __float2half(t[tx][nn]);
        }
    } else {
        // x: MM*CC floats = 1M float4; 1024 blocks (32x32) x 256 thr x 4 iters
        const size_t base = (size_t)(blockIdx.y * 32 + blockIdx.x) * 1024;
        #pragma unroll
        for (int k = 0; k < 4; k++) {
            const size_t i = base + threadIdx.x + k * 256;
            float4 v = ((const float4*)x)[i];
            uint2 uh;
            __half2 h0 = __floats2half2_rn(v.x, v.y);
            __half2 h1 = __floats2half2_rn(v.z, v.w);
            uh.x = *(uint32_t*)&h0;
            uh.y = *(uint32_t*)&h1;
            ((uint2*)g_ah)[i] = uh;
        }
    }
}

// ---------------------------------------------------------------------------
// fp16 HGEMM:  Y[128x128 tile] = A @ Wh^T + bias
// BK=64 stages, 3-stage cp.async pipeline, 2 CTAs/SM (regs capped at 128).
// 256 threads = 8 warps (2m x 4n), warp tile 64x32.
// ---------------------------------------------------------------------------
template<bool QKV>
__global__ void __launch_bounds__(256, 2) gemm_fp16(const float* __restrict__ bias0,
                                                    const float* __restrict__ bias1,
                                                    const float* __restrict__ bias2,
                                                    float* __restrict__ Yext)
{
    extern __shared__ char sm[];
    const uint32_t smb = smem_u32(sm);
    const int tid  = threadIdx.x;
    const int wid  = tid >> 5;
    const int lane = tid & 31;
    const int warpM = wid >> 2;
    const int warpN = wid & 3;
    const int z = QKV ? (int)blockIdx.z : 3;

    const __half* __restrict__ Ah = g_ah;
    const __half* __restrict__ Bh = g_wh[z];
    const float* bias = QKV ? (z == 0 ? bias0 : z == 1 ? bias1 : bias2) : bias0;

    const int rowBase = blockIdx.y * BM;
    const int colBase = blockIdx.x * BN;

    const uint32_t aLane = (uint32_t)((lane & 15) * PADK + (lane >> 4) * 8) * 2;
    const uint32_t bLane = (uint32_t)(((lane & 7) + ((lane >> 4) & 1) * 8) * PADK
                                      + ((lane >> 3) & 1) * 8) * 2;

    float acc[4][4][4];
    #pragma unroll
    for (int i = 0; i < 4; i++)
        #pragma unroll
        for (int j = 0; j < 4; j++)
            #pragma unroll
            for (int r = 0; r < 4; r++) acc[i][j][r] = 0.f;

    auto stage_load = [&](int s, int buf) {
        const int kb = s * BK;
        const uint32_t base = smb + buf * STAGEB;
        #pragma unroll
        for (int i = 0; i < 4; i++) {
            const int idx = tid + i * 256;       // 0..1023
            const int row = idx >> 3, ch = idx & 7;
            const uint32_t d = base + (uint32_t)(row * ROWB + ch * 16);
            cpa16(d + AH_OFF, (const char*)(Ah + (size_t)(rowBase + row) * CC + kb) + ch * 16);
            cpa16(d + BH_OFF, (const char*)(Bh + (size_t)(colBase + row) * CC + kb) + ch * 16);
        }
    };

    const int NSTAGE = CC / BK;       // 16
    stage_load(0, 0); cpa_commit();
    stage_load(1, 1); cpa_commit();

    int buf = 0;
    for (int kt = 0; kt < NSTAGE; kt++) {
        if (kt + 2 < NSTAGE) {
            int nb = buf + 2; if (nb >= 3) nb -= 3;
            stage_load(kt + 2, nb);
            cpa_commit();
            cpa_wait<2>();
        } else if (kt + 1 < NSTAGE) {
            cpa_wait<1>();
        } else {
            cpa_wait<0>();
        }
        __syncthreads();

        const uint32_t aBase = smb + buf * STAGEB + AH_OFF
                             + (uint32_t)(warpM * 64 * ROWB) + aLane;
        const uint32_t bBase = smb + buf * STAGEB + BH_OFF
                             + (uint32_t)(warpN * 32 * ROWB) + bLane;

        #pragma unroll
        for (int kk = 0; kk < BK; kk += 16) {
            uint32_t ah[4][4], bh[2][4];
            #pragma unroll
            for (int mt = 0; mt < 4; mt++)
                ldsm4(ah[mt], aBase + (uint32_t)(mt * 16 * ROWB + kk * 2));
            #pragma unroll
            for (int np = 0; np < 2; np++)
                ldsm4(bh[np], bBase + (uint32_t)(np * 16 * ROWB + kk * 2));
            #pragma unroll
            for (int mt = 0; mt < 4; mt++)
                #pragma unroll
                for (int nt = 0; nt < 4; nt++) {
                    const int np = nt >> 1, s2 = (nt & 1) * 2;
                    mma16816h(acc[mt][nt], ah[mt], bh[np][s2], bh[np][s2 + 1]);
                }
        }
        __syncthreads();
        buf++; if (buf == 3) buf = 0;
    }

    #pragma unroll
    for (int mt = 0; mt < 4; mt++) {
        const int row = rowBase + warpM * 64 + mt * 16 + (lane >> 2);
        #pragma unroll
        for (int nt = 0; nt < 4; nt++) {
            const int col = colBase + warpN * 32 + nt * 8 + (lane & 3) * 2;
            const float2 b2 = *(const float2*)(bias + col);
            float v00 = acc[mt][nt][0] + b2.x, v01 = acc[mt][nt][1] + b2.y;
            float v10 = acc[mt][nt][2] + b2.x, v11 = acc[mt][nt][3] + b2.y;
            if constexpr (!QKV) {
                float2 o0 = {v00, v01}, o1 = {v10, v11};
                *(float2*)(Yext + (size_t)row * CC + col)       = o0;
                *(float2*)(Yext + (size_t)(row + 8) * CC + col) = o1;
            } else {
                __half* dst = (z == 0) ? g_qh : (z == 1) ? g_kh : g_vh;
                if (z == 0) { v00 *= SCQ; v01 *= SCQ; v10 *= SCQ; v11 *= SCQ; }
                *(__half2*)(dst + (size_t)row * CC + col)       = __floats2half2_rn(v00, v01);
                *(__half2*)(dst + (size_t)(row + 8) * CC + col) = __floats2half2_rn(v10, v11);
            }
        }
    }
}

// ---------------------------------------------------------------------------
// Tensor-core causal flash attention (R13 math; 3-buffer KV ring with a
// SINGLE __syncthreads per tile — warps may skew up to a full tile, so
// softmax of one warp overlaps mma of the others).
// AQ=64, 4 warps, 4 CTAs/SM, Q via direct LDG, lane-local l.
// ---------------------------------------------------------------------------
__global__ void __launch_bounds__(128, 4) attn_tc()
{
    extern __shared__ char sm[];
    const uint32_t smb = smem_u32(sm);
    const int tid = threadIdx.x, wid = tid >> 5, lane = tid & 31;
    const int qb = (int)(gridDim.x - 1 - blockIdx.x) * AQ;   // heavy CTAs first
    const int h = blockIdx.y, b = blockIdx.z;
    const size_t rowOff = (size_t)(b * TT) * CC + h * DD;
    const int wr0 = qb + wid * 16;

    auto stageKV = [&](int t, int bufi) {
        int kb = t * AKV;
        #pragma unroll
        for (int i = 0; i < 8; i++) {
            int idx = tid + i * 128;             // 0..1023
            int mv = idx >> 9, r = (idx >> 3) & 63, ch = idx & 7;
            const __half* src = (mv ? g_vh : g_kh) + rowOff + (size_t)(kb + r) * CC + ch * 8;
            cpa16(smb + (uint32_t)(bufi * PAIRB + mv * KVHALF + r * AST + ch * 16), src);
        }
    };
    stageKV(0, 0);
    cpa_commit();

    // ---- Q fragments via direct LDG (canonical m16n8k16 A-frag layout) ----
    uint32_t qf[4][4];
    {
        const __half* q0 = g_qh + rowOff + (size_t)(wr0 + (lane >> 2)) * CC + (lane & 3) * 2;
        #pragma unroll
        for (int ks = 0; ks < 4; ks++) {
            qf[ks][0] = *(const uint32_t*)(q0 + ks * 16);
            qf[ks][1] = *(const uint32_t*)(q0 + 8 * CC + ks * 16);
            qf[ks][2] = *(const uint32_t*)(q0 + ks * 16 + 8);
            qf[ks][3] = *(const uint32_t*)(q0 + 8 * CC + ks * 16 + 8);
        }
    }

    float O[8][4];
    #pragma unroll
    for (int i = 0; i < 8; i++)
        #pragma unroll
        for (int j = 0; j < 4; j++) O[i][j] = 0.f;
    float m0 = -1e30f, m1 = -1e30f, l0 = 0.f, l1 = 0.f;   // l: lane-local partials

    const int ntiles = qb / AKV + 1;
    const uint32_t klane = (uint32_t)(((lane & 7) + ((lane >> 4) & 1) * 8) * AST
                                      + ((lane >> 3) & 1) * 16);
    const uint32_t vlane = (uint32_t)(((lane & 7) + ((lane >> 3) & 1) * 8) * AST
                                      + ((lane >> 4) & 1) * 16);

    int buf = 0;
    for (int t = 0; t < ntiles; t++) {
        // Prefetch next tile into ring slot (t+1)%3 = (t-2)%3's buffer; all
        // warps are guaranteed past compute(t-2) once they pass this tile's
        // sync, so the overwrite is safe with a single barrier per tile.
        if (t + 1 < ntiles) {
            int nb = buf + 1; if (nb == 3) nb = 0;
            stageKV(t + 1, nb);
            cpa_commit();
            cpa_wait<1>();
        } else {
            cpa_wait<0>();
        }
        __syncthreads();   // the ONLY barrier per tile

        const int kb = t * AKV;

        // ---- scores S = Q . K^T ----
        float S[8][4];
        #pragma unroll
        for (int i = 0; i < 8; i++)
            #pragma unroll
            for (int j = 0; j < 4; j++) S[i][j] = 0.f;

        const uint32_t kbase = smb + (uint32_t)(buf * PAIRB) + klane;
        #pragma unroll
        for (int nn = 0; nn < 4; nn++)
            #pragma unroll
            for (int ks = 0; ks < 4; ks++) {
                uint32_t kf[4];
                ldsm4(kf, kbase + (uint32_t)(nn * 16 * AST + ks * 32));
                mma16816h(S[2*nn],   qf[ks], kf[0], kf[1]);
                mma16816h(S[2*nn+1], qf[ks], kf[2], kf[3]);
            }

        // ---- causal mask (diagonal tile only) ----
        if (kb + 63 > wr0) {
            const int r0 = wr0 + (lane >> 2), r1 = r0 + 8;
            #pragma unroll
            for (int sf = 0; sf < 8; sf++) {
                const int c = kb + sf * 8 + (lane & 3) * 2;
                if (c     > r0) S[sf][0] = -1e30f;
                if (c + 1 > r0) S[sf][1] = -1e30f;
                if (c     > r1) S[sf][2] = -1e30f;
                if (c + 1 > r1) S[sf][3] = -1e30f;
            }
        }

        // ---- online softmax: row max (only the max needs cross-lane) ----
        float mx0 = -1e30f, mx1 = -1e30f;
        #pragma unroll
        for (int sf = 0; sf < 8; sf++) {
            mx0 = fmaxf(mx0, fmaxf(S[sf][0], S[sf][1]));
            mx1 = fmaxf(mx1, fmaxf(S[sf][2], S[sf][3]));
        }
        mx0 = fmaxf(mx0, __shfl_xor_sync(0xffffffffu, mx0, 1));
        mx0 = fmaxf(mx0, __shfl_xor_sync(0xffffffffu, mx0, 2));
        mx1 = fmaxf(mx1, __shfl_xor_sync(0xffffffffu, mx1, 1));
        mx1 = fmaxf(mx1, __shfl_xor_sync(0xffffffffu, mx1, 2));
        const float nm0 = fmaxf(m0, mx0), nm1 = fmaxf(m1, mx1);
        const float corr0 = ex2f(m0 - nm0), corr1 = ex2f(m1 - nm1);
        m0 = nm0; m1 = nm1;

        // ---- exp + lane-local partial sums (no shuffles here) ----
        float sum0 = 0.f, sum1 = 0.f;
        #pragma unroll
        for (int sf = 0; sf < 8; sf++) {
            S[sf][0] = ex2f(S[sf][0] - nm0);
            S[sf][1] = ex2f(S[sf][1] - nm0);
            S[sf][2] = ex2f(S[sf][2] - nm1);
            S[sf][3] = ex2f(S[sf][3] - nm1);
            sum0 += S[sf][0] + S[sf][1];
            sum1 += S[sf][2] + S[sf][3];
        }
        l0 = l0 * corr0 + sum0;
        l1 = l1 * corr1 + sum1;

        #pragma unroll
        for (int sf = 0; sf < 8; sf++) {
            O[sf][0] *= corr0; O[sf][1] *= corr0;
            O[sf][2] *= corr1; O[sf][3] *= corr1;
        }

        // ---- pack P into fp16 A-fragments ----
        uint32_t pa[4][4];
        #pragma unroll
        for (int j = 0; j < 4; j++) {
            #pragma unroll
            for (int q = 0; q < 4; q++) {
                const int sf = 2 * j + (q >> 1);
                const int e  = (q & 1) * 2;
                pa[j][q] = packh2(S[sf][e], S[sf][e + 1]);
            }
        }

        // ---- O += P . V ----
        const uint32_t vbase = smb + (uint32_t)(buf * PAIRB + KVHALF) + vlane;
        #pragma unroll
        for (int dd = 0; dd < 4; dd++)
            #pragma unroll
            for (int j = 0; j < 4; j++) {
                uint32_t vf[4];
                ldsm4t(vf, vbase + (uint32_t)(j * 16 * AST + dd * 32));
                mma16816h(O[2*dd],   pa[j], vf[0], vf[1]);
                mma16816h(O[2*dd+1], pa[j], vf[2], vf[3]);
            }

        buf++; if (buf == 3) buf = 0;
    }

    // ---- cross-lane l reduction, once ----
    l0 += __shfl_xor_sync(0xffffffffu, l0, 1);
    l0 += __shfl_xor_sync(0xffffffffu, l0, 2);
    l1 += __shfl_xor_sync(0xffffffffu, l1, 1);
    l1 += __shfl_xor_sync(0xffffffffu, l1, 2);

    // ---- epilogue: normalize, convert fp16, store into g_ah ----
    const float inv0 = 1.f / l0, inv1 = 1.f / l1;
    const int row0 = qb + wid * 16 + (lane >> 2);
    #pragma unroll
    for (int sf = 0; sf < 8; sf++) {
        const int col = h * DD + sf * 8 + (lane & 3) * 2;
        *(__half2*)(g_ah + (size_t)(b * TT + row0) * CC + col) =
            __floats2half2_rn(O[sf][0] * inv0, O[sf][1] * inv0);
        *(__half2*)(g_ah + (size_t)(b * TT + row0 + 8) * CC + col) =
            __floats2half2_rn(O[sf][2] * inv1, O[sf][3] * inv1);
    }
}

// ---------------------------------------------------------------------------
// Launch sequence
// ---------------------------------------------------------------------------
extern "C" void kernel_launch(void* const* d_in, const int* in_sizes, int n_in,
                              void* d_out, int out_size)
{
    const float* x  = (const float*)d_in[0];
    const float* Wq = (const float*)d_in[1];
    const float* bq = (const float*)d_in[2];
    const float* Wk = (const float*)d_in[3];
    const float* bk = (const float*)d_in[4];
    const float* Wv = (const float*)d_in[5];
    const float* bv = (const float*)d_in[6];
    const float* Wo = (const float*)d_in[7];
    const float* bo = (const float*)d_in[8];
    float* out = (float*)d_out;

    cudaFuncSetAttribute(gemm_fp16<true>,  cudaFuncAttributeMaxDynamicSharedMemorySize, GSMEM_TOTAL);
    cudaFuncSetAttribute(gemm_fp16<false>, cudaFuncAttributeMaxDynamicSharedMemorySize, GSMEM_TOTAL);
    cudaFuncSetAttribute(attn_tc,          cudaFuncAttributeMaxDynamicSharedMemorySize, ASMEM);

    const dim3 gcv(CC / 32, CC / 32, 5);       // fused weight-transpose + x-convert
    const dim3 gqkv(CC / BN, MM / BM, 3);
    const dim3 go(CC / BN, MM / BM);

    cvt_all<<<gcv, 256>>>(x, Wq, Wk, Wv, Wo);

    gemm_fp16<true><<<gqkv, 256, GSMEM_TOTAL>>>(bq, bk, bv, nullptr);

    const dim3 ga(TT / AQ, HH, BB);
    attn_tc<<<ga, 128, ASMEM>>>();

    gemm_fp16<false><<<go, 256, GSMEM_TOTAL>>>(bo, nullptr, nullptr, out);
}

// round 17
// speedup vs baseline: 1.1649x; 1.0684x over previous
#include <cuda_runtime.h>
#include <cuda_fp16.h>
#include <cstdint>

#define BB 2
#define TT 2048
#define CC 1024
#define HH 16
#define DD 64
#define MM (BB*TT)

// ---- projection GEMM tiling ----
#define BM 128
#define BN 128
#define BK 64
#define PADK 72                 // smem row stride in halves (144 B), conflict-free
#define ROWB (PADK*2)           // 144 bytes
#define AH_OFF 0
#define BH_OFF (128*ROWB)       // 18432
#define STAGEB (2*128*ROWB)     // 36864
#define GSMEM_TOTAL (3*STAGEB)  // 110592 B  (x2 CTAs <= carveout)

// ---- attention tiling: AQ=64, 4 warps, 4 CTAs/SM; Q direct-LDG ----
// 3-buffer KV ring, ONE __syncthreads per tile.
#define AQ  64
#define AKV 64
#define AST 144
#define KVHALF (64*AST)         // 9216: V offset within a buffer
#define PAIRB (2*64*AST)        // 18432 per ring buffer (K+V)
#define ASMEM (3*PAIRB)         // 55296  (x4 CTAs = 221184 <= carveout)

#define SCQ (0.125f * 1.44269504088896340736f)   // 1/sqrt(D) * log2(e)

// ---------------------------------------------------------------------------
// Scratch (allocation-free device globals) — all fp16
// ---------------------------------------------------------------------------
__device__ __align__(256) __half g_qh[MM*CC];    // Q * 0.125*log2e
__device__ __align__(256) __half g_kh[MM*CC];
__device__ __align__(256) __half g_vh[MM*CC];
__device__ __align__(256) __half g_ah[MM*CC];    // A operand (x, later att out)
__device__ __align__(256) __half g_wh[4][CC*CC]; // W transposed [n][k], fp16

// ---------------------------------------------------------------------------
// PTX helpers (baseline sm_80+ features only)
// ---------------------------------------------------------------------------
__device__ __forceinline__ uint32_t smem_u32(const void* p) {
    uint32_t a;
    asm("{ .reg .u64 t; cvta.to.shared.u64 t, %1; cvt.u32.u64 %0, t; }" : "=r"(a) : "l"(p));
    return a;
}
__device__ __forceinline__ void cpa16(uint32_t dst, const void* src) {
    asm volatile("cp.async.cg.shared.global [%0], [%1], 16;" :: "r"(dst), "l"(src));
}
__device__ __forceinline__ void cpa_commit() {
    asm volatile("cp.async.commit_group;" ::: "memory");
}
template<int N>
__device__ __forceinline__ void cpa_wait() {
    asm volatile("cp.async.wait_group %0;" :: "n"(N) : "memory");
}
__device__ __forceinline__ void ldsm4(uint32_t* r, uint32_t addr) {
    asm volatile("ldmatrix.sync.aligned.m8n8.x4.shared.b16 {%0,%1,%2,%3}, [%4];"
        : "=r"(r[0]), "=r"(r[1]), "=r"(r[2]), "=r"(r[3]) : "r"(addr));
}
__device__ __forceinline__ void ldsm4t(uint32_t* r, uint32_t addr) {
    asm volatile("ldmatrix.sync.aligned.m8n8.x4.trans.shared.b16 {%0,%1,%2,%3}, [%4];"
        : "=r"(r[0]), "=r"(r[1]), "=r"(r[2]), "=r"(r[3]) : "r"(addr));
}
__device__ __forceinline__ void mma16816h(float* c, const uint32_t* a,
                                          uint32_t b0, uint32_t b1) {
    asm volatile("mma.sync.aligned.m16n8k16.row.col.f32.f16.f16.f32 "
        "{%0,%1,%2,%3}, {%4,%5,%6,%7}, {%8,%9}, {%0,%1,%2,%3};"
        : "+f"(c[0]), "+f"(c[1]), "+f"(c[2]), "+f"(c[3])
        : "r"(a[0]), "r"(a[1]), "r"(a[2]), "r"(a[3]), "r"(b0), "r"(b1));
}
__device__ __forceinline__ float ex2f(float x) {
    float r;
    asm("ex2.approx.ftz.f32 %0, %1;" : "=f"(r) : "f"(x));
    return r;
}
__device__ __forceinline__ uint32_t packh2(float a, float b) {
    __half2 h = __floats2half2_rn(a, b);
    return *(uint32_t*)&h;
}

// ---------------------------------------------------------------------------
// Fused conversions: z=0..3 transpose W[z] fp32->fp16 [n][k]; z=4 converts x.
// ---------------------------------------------------------------------------
__global__ void __launch_bounds__(256) cvt_all(const float* __restrict__ x,
                                               const float* __restrict__ W0,
                                               const float* __restrict__ W1,
                                               const float* __restrict__ W2,
                                               const float* __restrict__ W3)
{
    const int z = blockIdx.z;
    if (z < 4) {
        const float* Ws[4] = {W0, W1, W2, W3};
        const float* W = Ws[z];
        __half* dst = g_wh[z];
        __shared__ float t[32][33];
        const int n0 = blockIdx.x * 32, k0 = blockIdx.y * 32;
        const int tx = threadIdx.x & 31, ty = threadIdx.x >> 5;
        #pragma unroll
        for (int i = 0; i < 4; i++)
            t[ty + 8*i][tx] = W[(size_t)(k0 + ty + 8*i) * CC + n0 + tx];
        __syncthreads();
        #pragma unroll
        for (int i = 0; i < 4; i++) {
            int nn = ty + 8*i;
            dst[(size_t)(n0 + nn) * CC + k0 + tx] = __float2half(t[tx][nn]);
        }
    } else {
        // x: MM*CC floats = 1M float4; 1024 blocks (32x32) x 256 thr x 4 iters
        const size_t base = (size_t)(blockIdx.y * 32 + blockIdx.x) * 1024;
        #pragma unroll
        for (int k = 0; k < 4; k++) {
            const size_t i = base + threadIdx.x + k * 256;
            float4 v = ((const float4*)x)[i];
            uint2 uh;
            __half2 h0 = __floats2half2_rn(v.x, v.y);
            __half2 h1 = __floats2half2_rn(v.z, v.w);
            uh.x = *(uint32_t*)&h0;
            uh.y = *(uint32_t*)&h1;
            ((uint2*)g_ah)[i] = uh;
        }
    }
}

// ---------------------------------------------------------------------------
// fp16 HGEMM:  Y[128x128 tile] = A @ Wh^T + bias
// BK=64 stages, 3-buffer ring at prefetch depth 1 with a SINGLE
// __syncthreads per stage (write of stage kt+1 lands in the buffer of
// stage kt-2, which every warp finished before sync(kt-1)).
// 2 CTAs/SM (regs capped 128), 8 warps (2m x 4n), warp tile 64x32.
// ---------------------------------------------------------------------------
template<bool QKV>
__global__ void __launch_bounds__(256, 2) gemm_fp16(const float* __restrict__ bias0,
                                                    const float* __restrict__ bias1,
                                                    const float* __restrict__ bias2,
                                                    float* __restrict__ Yext)
{
    extern __shared__ char sm[];
    const uint32_t smb = smem_u32(sm);
    const int tid  = threadIdx.x;
    const int wid  = tid >> 5;
    const int lane = tid & 31;
    const int warpM = wid >> 2;
    const int warpN = wid & 3;
    const int z = QKV ? (int)blockIdx.z : 3;

    const __half* __restrict__ Ah = g_ah;
    const __half* __restrict__ Bh = g_wh[z];
    const float* bias = QKV ? (z == 0 ? bias0 : z == 1 ? bias1 : bias2) : bias0;

    const int rowBase = blockIdx.y * BM;
    const int colBase = blockIdx.x * BN;

    const uint32_t aLane = (uint32_t)((lane & 15) * PADK + (lane >> 4) * 8) * 2;
    const uint32_t bLane = (uint32_t)(((lane & 7) + ((lane >> 4) & 1) * 8) * PADK
                                      + ((lane >> 3) & 1) * 8) * 2;

    float acc[4][4][4];
    #pragma unroll
    for (int i = 0; i < 4; i++)
        #pragma unroll
        for (int j = 0; j < 4; j++)
            #pragma unroll
            for (int r = 0; r < 4; r++) acc[i][j][r] = 0.f;

    auto stage_load = [&](int s, int buf) {
        const int kb = s * BK;
        const uint32_t base = smb + buf * STAGEB;
        #pragma unroll
        for (int i = 0; i < 4; i++) {
            const int idx = tid + i * 256;       // 0..1023
            const int row = idx >> 3, ch = idx & 7;
            const uint32_t d = base + (uint32_t)(row * ROWB + ch * 16);
            cpa16(d + AH_OFF, (const char*)(Ah + (size_t)(rowBase + row) * CC + kb) + ch * 16);
            cpa16(d + BH_OFF, (const char*)(Bh + (size_t)(colBase + row) * CC + kb) + ch * 16);
        }
    };

    const int NSTAGE = CC / BK;       // 16
    stage_load(0, 0); cpa_commit();

    int buf = 0;
    for (int kt = 0; kt < NSTAGE; kt++) {
        if (kt + 1 < NSTAGE) {
            int nb = buf + 1; if (nb == 3) nb = 0;
            stage_load(kt + 1, nb);
            cpa_commit();
            cpa_wait<1>();
        } else {
            cpa_wait<0>();
        }
        __syncthreads();   // the ONLY barrier per stage

        const uint32_t aBase = smb + buf * STAGEB + AH_OFF
                             + (uint32_t)(warpM * 64 * ROWB) + aLane;
        const uint32_t bBase = smb + buf * STAGEB + BH_OFF
                             + (uint32_t)(warpN * 32 * ROWB) + bLane;

        #pragma unroll
        for (int kk = 0; kk < BK; kk += 16) {
            uint32_t ah[4][4], bh[2][4];
            #pragma unroll
            for (int mt = 0; mt < 4; mt++)
                ldsm4(ah[mt], aBase + (uint32_t)(mt * 16 * ROWB + kk * 2));
            #pragma unroll
            for (int np = 0; np < 2; np++)
                ldsm4(bh[np], bBase + (uint32_t)(np * 16 * ROWB + kk * 2));
            #pragma unroll
            for (int mt = 0; mt < 4; mt++)
                #pragma unroll
                for (int nt = 0; nt < 4; nt++) {
                    const int np = nt >> 1, s2 = (nt & 1) * 2;
                    mma16816h(acc[mt][nt], ah[mt], bh[np][s2], bh[np][s2 + 1]);
                }
        }
        buf++; if (buf == 3) buf = 0;
    }

    #pragma unroll
    for (int mt = 0; mt < 4; mt++) {
        const int row = rowBase + warpM * 64 + mt * 16 + (lane >> 2);
        #pragma unroll
        for (int nt = 0; nt < 4; nt++) {
            const int col = colBase + warpN * 32 + nt * 8 + (lane & 3) * 2;
            const float2 b2 = *(const float2*)(bias + col);
            float v00 = acc[mt][nt][0] + b2.x, v01 = acc[mt][nt][1] + b2.y;
            float v10 = acc[mt][nt][2] + b2.x, v11 = acc[mt][nt][3] + b2.y;
            if constexpr (!QKV) {
                float2 o0 = {v00, v01}, o1 = {v10, v11};
                *(float2*)(Yext + (size_t)row * CC + col)       = o0;
                *(float2*)(Yext + (size_t)(row + 8) * CC + col) = o1;
            } else {
                __half* dst = (z == 0) ? g_qh : (z == 1) ? g_kh : g_vh;
                if (z == 0) { v00 *= SCQ; v01 *= SCQ; v10 *= SCQ; v11 *= SCQ; }
                *(__half2*)(dst + (size_t)row * CC + col)       = __floats2half2_rn(v00, v01);
                *(__half2*)(dst + (size_t)(row + 8) * CC + col) = __floats2half2_rn(v10, v11);
            }
        }
    }
}

// ---------------------------------------------------------------------------
// Tensor-core causal flash attention (R16: 3-buffer KV ring, single
// __syncthreads per tile).  AQ=64, 4 warps, 4 CTAs/SM, Q direct-LDG,
// lane-local l.
// ---------------------------------------------------------------------------
__global__ void __launch_bounds__(128, 4) attn_tc()
{
    extern __shared__ char sm[];
    const uint32_t smb = smem_u32(sm);
    const int tid = threadIdx.x, wid = tid >> 5, lane = tid & 31;
    const int qb = (int)(gridDim.x - 1 - blockIdx.x) * AQ;   // heavy CTAs first
    const int h = blockIdx.y, b = blockIdx.z;
    const size_t rowOff = (size_t)(b * TT) * CC + h * DD;
    const int wr0 = qb + wid * 16;

    auto stageKV = [&](int t, int bufi) {
        int kb = t * AKV;
        #pragma unroll
        for (int i = 0; i < 8; i++) {
            int idx = tid + i * 128;             // 0..1023
            int mv = idx >> 9, r = (idx >> 3) & 63, ch = idx & 7;
            const __half* src = (mv ? g_vh : g_kh) + rowOff + (size_t)(kb + r) * CC + ch * 8;
            cpa16(smb + (uint32_t)(bufi * PAIRB + mv * KVHALF + r * AST + ch * 16), src);
        }
    };
    stageKV(0, 0);
    cpa_commit();

    // ---- Q fragments via direct LDG (canonical m16n8k16 A-frag layout) ----
    uint32_t qf[4][4];
    {
        const __half* q0 = g_qh + rowOff + (size_t)(wr0 + (lane >> 2)) * CC + (lane & 3) * 2;
        #pragma unroll
        for (int ks = 0; ks < 4; ks++) {
            qf[ks][0] = *(const uint32_t*)(q0 + ks * 16);
            qf[ks][1] = *(const uint32_t*)(q0 + 8 * CC + ks * 16);
            qf[ks][2] = *(const uint32_t*)(q0 + ks * 16 + 8);
            qf[ks][3] = *(const uint32_t*)(q0 + 8 * CC + ks * 16 + 8);
        }
    }

    float O[8][4];
    #pragma unroll
    for (int i = 0; i < 8; i++)
        #pragma unroll
        for (int j = 0; j < 4; j++) O[i][j] = 0.f;
    float m0 = -1e30f, m1 = -1e30f, l0 = 0.f, l1 = 0.f;   // l: lane-local partials

    const int ntiles = qb / AKV + 1;
    const uint32_t klane = (uint32_t)(((lane & 7) + ((lane >> 4) & 1) * 8) * AST
                                      + ((lane >> 3) & 1) * 16);
    const uint32_t vlane = (uint32_t)(((lane & 7) + ((lane >> 3) & 1) * 8) * AST
                                      + ((lane >> 4) & 1) * 16);

    int buf = 0;
    for (int t = 0; t < ntiles; t++) {
        if (t + 1 < ntiles) {
            int nb = buf + 1; if (nb == 3) nb = 0;
            stageKV(t + 1, nb);
            cpa_commit();
            cpa_wait<1>();
        } else {
            cpa_wait<0>();
        }
        __syncthreads();   // the ONLY barrier per tile

        const int kb = t * AKV;

        // ---- scores S = Q . K^T ----
        float S[8][4];
        #pragma unroll
        for (int i = 0; i < 8; i++)
            #pragma unroll
            for (int j = 0; j < 4; j++) S[i][j] = 0.f;

        const uint32_t kbase = smb + (uint32_t)(buf * PAIRB) + klane;
        #pragma unroll
        for (int nn = 0; nn < 4; nn++)
            #pragma unroll
            for (int ks = 0; ks < 4; ks++) {
                uint32_t kf[4];
                ldsm4(kf, kbase + (uint32_t)(nn * 16 * AST + ks * 32));
                mma16816h(S[2*nn],   qf[ks], kf[0], kf[1]);
                mma16816h(S[2*nn+1], qf[ks], kf[2], kf[3]);
            }

        // ---- causal mask (diagonal tile only) ----
        if (kb + 63 > wr0) {
            const int r0 = wr0 + (lane >> 2), r1 = r0 + 8;
            #pragma unroll
            for (int sf = 0; sf < 8; sf++) {
                const int c = kb + sf * 8 + (lane & 3) * 2;
                if (c     > r0) S[sf][0] = -1e30f;
                if (c + 1 > r0) S[sf][1] = -1e30f;
                if (c     > r1) S[sf][2] = -1e30f;
                if (c + 1 > r1) S[sf][3] = -1e30f;
            }
        }

        // ---- online softmax: row max (only the max needs cross-lane) ----
        float mx0 = -1e30f, mx1 = -1e30f;
        #pragma unroll
        for (int sf = 0; sf < 8; sf++) {
            mx0 = fmaxf(mx0, fmaxf(S[sf][0], S[sf][1]));
            mx1 = fmaxf(mx1, fmaxf(S[sf][2], S[sf][3]));
        }
        mx0 = fmaxf(mx0, __shfl_xor_sync(0xffffffffu, mx0, 1));
        mx0 = fmaxf(mx0, __shfl_xor_sync(0xffffffffu, mx0, 2));
        mx1 = fmaxf(mx1, __shfl_xor_sync(0xffffffffu, mx1, 1));
        mx1 = fmaxf(mx1, __shfl_xor_sync(0xffffffffu, mx1, 2));
        const float nm0 = fmaxf(m0, mx0), nm1 = fmaxf(m1, mx1);
        const float corr0 = ex2f(m0 - nm0), corr1 = ex2f(m1 - nm1);
        m0 = nm0; m1 = nm1;

        // ---- exp + lane-local partial sums (no shuffles here) ----
        float sum0 = 0.f, sum1 = 0.f;
        #pragma unroll
        for (int sf = 0; sf < 8; sf++) {
            S[sf][0] = ex2f(S[sf][0] - nm0);
            S[sf][1] = ex2f(S[sf][1] - nm0);
            S[sf][2] = ex2f(S[sf][2] - nm1);
            S[sf][3] = ex2f(S[sf][3] - nm1);
            sum0 += S[sf][0] + S[sf][1];
            sum1 += S[sf][2] + S[sf][3];
        }
        l0 = l0 * corr0 + sum0;
        l1 = l1 * corr1 + sum1;

        #pragma unroll
        for (int sf = 0; sf < 8; sf++) {
            O[sf][0] *= corr0; O[sf][1] *= corr0;
            O[sf][2] *= corr1; O[sf][3] *= corr1;
        }

        // ---- pack P into fp16 A-fragments ----
        uint32_t pa[4][4];
        #pragma unroll
        for (int j = 0; j < 4; j++) {
            #pragma unroll
            for (int q = 0; q < 4; q++) {
                const int sf = 2 * j + (q >> 1);
                const int e  = (q & 1) * 2;
                pa[j][q] = packh2(S[sf][e], S[sf][e + 1]);
            }
        }

        // ---- O += P . V ----
        const uint32_t vbase = smb + (uint32_t)(buf * PAIRB + KVHALF) + vlane;
        #pragma unroll
        for (int dd = 0; dd < 4; dd++)
            #pragma unroll
            for (int j = 0; j < 4; j++) {
                uint32_t vf[4];
                ldsm4t(vf, vbase + (uint32_t)(j * 16 * AST + dd * 32));
                mma16816h(O[2*dd],   pa[j], vf[0], vf[1]);
                mma16816h(O[2*dd+1], pa[j], vf[2], vf[3]);
            }

        buf++; if (buf == 3) buf = 0;
    }

    // ---- cross-lane l reduction, once ----
    l0 += __shfl_xor_sync(0xffffffffu, l0, 1);
    l0 += __shfl_xor_sync(0xffffffffu, l0, 2);
    l1 += __shfl_xor_sync(0xffffffffu, l1, 1);
    l1 += __shfl_xor_sync(0xffffffffu, l1, 2);

    // ---- epilogue: normalize, convert fp16, store into g_ah ----
    const float inv0 = 1.f / l0, inv1 = 1.f / l1;
    const int row0 = qb + wid * 16 + (lane >> 2);
    #pragma unroll
    for (int sf = 0; sf < 8; sf++) {
        const int col = h * DD + sf * 8 + (lane & 3) * 2;
        *(__half2*)(g_ah + (size_t)(b * TT + row0) * CC + col) =
            __floats2half2_rn(O[sf][0] * inv0, O[sf][1] * inv0);
        *(__half2*)(g_ah + (size_t)(b * TT + row0 + 8) * CC + col) =
            __floats2half2_rn(O[sf][2] * inv1, O[sf][3] * inv1);
    }
}

// ---------------------------------------------------------------------------
// Launch sequence
// ---------------------------------------------------------------------------
extern "C" void kernel_launch(void* const* d_in, const int* in_sizes, int n_in,
                              void* d_out, int out_size)
{
    const float* x  = (const float*)d_in[0];
    const float* Wq = (const float*)d_in[1];
    const float* bq = (const float*)d_in[2];
    const float* Wk = (const float*)d_in[3];
    const float* bk = (const float*)d_in[4];
    const float* Wv = (const float*)d_in[5];
    const float* bv = (const float*)d_in[6];
    const float* Wo = (const float*)d_in[7];
    const float* bo = (const float*)d_in[8];
    float* out = (float*)d_out;

    cudaFuncSetAttribute(gemm_fp16<true>,  cudaFuncAttributeMaxDynamicSharedMemorySize, GSMEM_TOTAL);
    cudaFuncSetAttribute(gemm_fp16<false>, cudaFuncAttributeMaxDynamicSharedMemorySize, GSMEM_TOTAL);
    cudaFuncSetAttribute(attn_tc,          cudaFuncAttributeMaxDynamicSharedMemorySize, ASMEM);

    const dim3 gcv(CC / 32, CC / 32, 5);       // fused weight-transpose + x-convert
    const dim3 gqkv(CC / BN, MM / BM, 3);
    const dim3 go(CC / BN, MM / BM);

    cvt_all<<<gcv, 256>>>(x, Wq, Wk, Wv, Wo);

    gemm_fp16<true><<<gqkv, 256, GSMEM_TOTAL>>>(bq, bk, bv, nullptr);

    const dim3 ga(TT / AQ, HH, BB);
    attn_tc<<<ga, 128, ASMEM>>>();

    gemm_fp16<false><<<go, 256, GSMEM_TOTAL>>>(bo, nullptr, nullptr, out);
}